// round 3
// baseline (speedup 1.0000x reference)
#include <cuda_runtime.h>
#include <cuda_bf16.h>

// binary contrastive loss, fully fused single kernel:
//   sim0[i] = <x[i],x[i]>/temp ; sim1[i] = <x[i],x[samples[i]]>/temp
//   diff = sim0-sim1 ; label = (y[i]!=y[samples[i]])
//   loss = -log(sigmoid(diff)+eps)*label - log(1-sigmoid(diff)+eps)*(1-label)
//   out  = mean(loss)
//
// x: [B=16384, D=2048] fp32 ; y, samples: int32 ; out: 1 fp32 scalar.
// One block per row; float4 loads; block reduce; per-block loss into a
// __device__ partial array; last-finished block (monotonic ticket counter,
// no reset needed -> graph-capturable & deterministic) reduces partials and
// writes the mean. Single launch per replay (also makes ncu -s5 -c1 land on
// the real kernel).

#define TEMP_INV 10.0f
#define EPS 1e-5f
#define B_MAX 16384

__device__ float g_partial[B_MAX];
__device__ unsigned int g_ticket;   // zero at load; +B per launch, monotonic

__global__ __launch_bounds__(256) void fused_loss_kernel(
    const float* __restrict__ x,
    const int* __restrict__ y,
    const int* __restrict__ samples,
    float* __restrict__ out,
    int B, int D)
{
    const int i = blockIdx.x;
    const int j = samples[i];

    const float4* __restrict__ xi = reinterpret_cast<const float4*>(x + (size_t)i * D);
    const float4* __restrict__ xj = reinterpret_cast<const float4*>(x + (size_t)j * D);

    float s0 = 0.0f, s1 = 0.0f;
    const int nvec = D >> 2;   // 512 float4 per row

    #pragma unroll 2
    for (int t = threadIdx.x; t < nvec; t += blockDim.x) {
        float4 a = xi[t];
        float4 b = xj[t];
        s0 = fmaf(a.x, a.x, s0); s0 = fmaf(a.y, a.y, s0);
        s0 = fmaf(a.z, a.z, s0); s0 = fmaf(a.w, a.w, s0);
        s1 = fmaf(a.x, b.x, s1); s1 = fmaf(a.y, b.y, s1);
        s1 = fmaf(a.z, b.z, s1); s1 = fmaf(a.w, b.w, s1);
    }

    // warp reduce
    #pragma unroll
    for (int o = 16; o > 0; o >>= 1) {
        s0 += __shfl_xor_sync(0xFFFFFFFFu, s0, o);
        s1 += __shfl_xor_sync(0xFFFFFFFFu, s1, o);
    }

    __shared__ float sh0[8], sh1[8];
    __shared__ bool  s_last;
    const int w = threadIdx.x >> 5;
    const int l = threadIdx.x & 31;
    if (l == 0) { sh0[w] = s0; sh1[w] = s1; }
    __syncthreads();

    if (threadIdx.x == 0) {
        #pragma unroll
        for (int k = 1; k < 8; k++) { s0 += sh0[k]; s1 += sh1[k]; }

        const float diff = (s0 - s1) * TEMP_INV;
        const float p = 1.0f / (1.0f + expf(-diff));
        const float label = (y[i] != y[j]) ? 1.0f : 0.0f;
        const float loss = -logf(p + EPS) * label
                           - logf(1.0f - p + EPS) * (1.0f - label);
        g_partial[i] = loss;
        __threadfence();                              // publish partial
        unsigned int t = atomicAdd(&g_ticket, 1u);
        s_last = ((t % (unsigned)B) == (unsigned)(B - 1));
    }
    __syncthreads();

    // last block to finish reduces all partials and writes the mean
    if (s_last) {
        __threadfence();                              // see all partials
        float acc = 0.0f;
        for (int k = threadIdx.x; k < B; k += blockDim.x)
            acc += g_partial[k];

        #pragma unroll
        for (int o = 16; o > 0; o >>= 1)
            acc += __shfl_xor_sync(0xFFFFFFFFu, acc, o);

        if (l == 0) sh0[w] = acc;
        __syncthreads();
        if (threadIdx.x == 0) {
            float total = 0.0f;
            #pragma unroll
            for (int k = 0; k < 8; k++) total += sh0[k];
            out[0] = total / (float)B;
        }
    }
}

extern "C" void kernel_launch(void* const* d_in, const int* in_sizes, int n_in,
                              void* d_out, int out_size)
{
    const float* x       = (const float*)d_in[0];
    const int*   y       = (const int*)d_in[1];
    const int*   samples = (const int*)d_in[2];
    float* out = (float*)d_out;

    const int B = in_sizes[1];                 // 16384
    const int D = in_sizes[0] / in_sizes[1];   // 2048

    fused_loss_kernel<<<B, 256>>>(x, y, samples, out, B, D);
}

// round 4
// speedup vs baseline: 1.5652x; 1.5652x over previous
#include <cuda_runtime.h>
#include <cuda_bf16.h>

// binary contrastive loss:
//   sim0[i] = <x[i],x[i]>/temp ; sim1[i] = <x[i],x[samples[i]]>/temp
//   diff = sim0-sim1 ; label = (y[i]!=y[samples[i]])
//   loss = mean over i of -log(sigmoid(diff)+eps)*label - log(1-sigmoid)*(1-label)
//
// x: [16384, 2048] fp32 ; y, samples: int32 ; out: 1 fp32.
//
// R3 lesson: __threadfence (GPU scope) emits MEMBAR.ALL + CCTL.IVALL (L1D
// flush) per block -> 2x regression. This version is fence-free:
//   kernel 1: one WARP per row (16 float4/lane -> high MLP, no __syncthreads),
//             butterfly-reduce, lane 0 atomicAdd of the row loss into g_accum
//             (L2 atomics are coherent, no fence required).
//   kernel 2: out = g_accum/B, then g_accum = 0 (reset for next graph replay;
//             stream order makes this race-free and deterministic).

#define TEMP_INV 10.0f
#define EPS 1e-5f

__device__ float g_accum;   // zero-initialized at module load; finalize resets it

__global__ __launch_bounds__(256) void loss_kernel(
    const float* __restrict__ x,
    const int* __restrict__ y,
    const int* __restrict__ samples,
    int B, int D)
{
    const int gwarp = (blockIdx.x * blockDim.x + threadIdx.x) >> 5;  // row id
    const int lane  = threadIdx.x & 31;
    if (gwarp >= B) return;

    const int i = gwarp;
    const int j = samples[i];     // same address for all lanes -> broadcast

    const float4* __restrict__ xi = reinterpret_cast<const float4*>(x + (size_t)i * D);
    const float4* __restrict__ xj = reinterpret_cast<const float4*>(x + (size_t)j * D);

    float s0 = 0.0f, s1 = 0.0f;
    const int nvec = D >> 2;      // 512 float4 per row, 16 per lane

    #pragma unroll 4
    for (int t = lane; t < nvec; t += 32) {
        float4 a = xi[t];
        float4 b = xj[t];
        s0 = fmaf(a.x, a.x, s0); s0 = fmaf(a.y, a.y, s0);
        s0 = fmaf(a.z, a.z, s0); s0 = fmaf(a.w, a.w, s0);
        s1 = fmaf(a.x, b.x, s1); s1 = fmaf(a.y, b.y, s1);
        s1 = fmaf(a.z, b.z, s1); s1 = fmaf(a.w, b.w, s1);
    }

    // warp butterfly reduce (all lanes end with the full sums)
    #pragma unroll
    for (int o = 16; o > 0; o >>= 1) {
        s0 += __shfl_xor_sync(0xFFFFFFFFu, s0, o);
        s1 += __shfl_xor_sync(0xFFFFFFFFu, s1, o);
    }

    if (lane == 0) {
        const float diff = (s0 - s1) * TEMP_INV;
        const float p = 1.0f / (1.0f + expf(-diff));
        const float label = (y[i] != y[j]) ? 1.0f : 0.0f;
        const float loss = -logf(p + EPS) * label
                           - logf(1.0f - p + EPS) * (1.0f - label);
        atomicAdd(&g_accum, loss);
    }
}

__global__ void finalize_kernel(float* __restrict__ out, float invB) {
    if (threadIdx.x == 0) {
        out[0] = g_accum * invB;
        g_accum = 0.0f;           // reset for the next graph replay
    }
}

extern "C" void kernel_launch(void* const* d_in, const int* in_sizes, int n_in,
                              void* d_out, int out_size)
{
    const float* x       = (const float*)d_in[0];
    const int*   y       = (const int*)d_in[1];
    const int*   samples = (const int*)d_in[2];
    float* out = (float*)d_out;

    const int B = in_sizes[1];                 // 16384
    const int D = in_sizes[0] / in_sizes[1];   // 2048

    const int warps_needed = B;                // one warp per row
    const int threads = 256;
    const int blocks = (warps_needed * 32 + threads - 1) / threads;  // 2048

    loss_kernel<<<blocks, threads>>>(x, y, samples, B, D);
    finalize_kernel<<<1, 32>>>(out, 1.0f / (float)B);
}

// round 5
// speedup vs baseline: 2.3975x; 1.5317x over previous
#include <cuda_runtime.h>
#include <cuda_bf16.h>

// binary contrastive loss:
//   sim0[i] = <x[i],x[i]>/temp ; sim1[i] = <x[i],x[samples[i]]>/temp
//   diff = sim0-sim1 ; label = (y[i]!=y[samples[i]])
//   out  = mean_i of -log(sigmoid+eps)*label - log(1-sigmoid+eps)*(1-label)
//
// x: [16384, 2048] fp32 ; y, samples: int32 ; out: 1 fp32.
//
// R3 lesson: no __threadfence (MEMBAR.ALL + CCTL.IVALL L1-flush killed perf).
// R4 lesson: warp-per-row loses to block-per-row (L1tex-queue spread).
// This round: PERSISTENT block-per-row.
//   - grid = 148*8 blocks, each strides over ~14 rows -> no wave transitions.
//   - per row: 256 threads x 2 float4 per operand, warp reduce,
//     double-buffered smem + ONE __syncthreads per row.
//   - loss accumulated in registers across the block's rows; ONE atomicAdd
//     per block at the end (1184 atomics total).
//   - finalize kernel: out = g_accum/B, then reset g_accum (kernel boundary
//     provides ordering; fence-free).

#define TEMP_INV 10.0f
#define EPS 1e-5f

__device__ float g_accum;   // zeroed at module load; finalize resets each replay

__global__ __launch_bounds__(256) void loss_kernel(
    const float* __restrict__ x,
    const int* __restrict__ y,
    const int* __restrict__ samples,
    int B, int D)
{
    __shared__ float sh0[16], sh1[16];   // two 8-slot buffers (parity)

    const int tid  = threadIdx.x;
    const int w    = tid >> 5;
    const int lane = tid & 31;
    const int nvec = D >> 2;             // 512 float4 per row
    const int t0   = tid;
    const int t1   = tid + 256;

    float blockLoss = 0.0f;
    int iter = 0;

    for (int i = blockIdx.x; i < B; i += gridDim.x, iter++) {
        const int j = samples[i];

        const float4* __restrict__ xi =
            reinterpret_cast<const float4*>(x + (size_t)i * D);
        const float4* __restrict__ xj =
            reinterpret_cast<const float4*>(x + (size_t)j * D);

        // front-batch all 4 loads (MLP=4/thread)
        float4 a0 = xi[t0];
        float4 a1 = xi[t1];
        float4 b0 = xj[t0];
        float4 b1 = xj[t1];

        float s0, s1;
        s0 = a0.x * a0.x;            s1 = a0.x * b0.x;
        s0 = fmaf(a0.y, a0.y, s0);   s1 = fmaf(a0.y, b0.y, s1);
        s0 = fmaf(a0.z, a0.z, s0);   s1 = fmaf(a0.z, b0.z, s1);
        s0 = fmaf(a0.w, a0.w, s0);   s1 = fmaf(a0.w, b0.w, s1);
        s0 = fmaf(a1.x, a1.x, s0);   s1 = fmaf(a1.x, b1.x, s1);
        s0 = fmaf(a1.y, a1.y, s0);   s1 = fmaf(a1.y, b1.y, s1);
        s0 = fmaf(a1.z, a1.z, s0);   s1 = fmaf(a1.z, b1.z, s1);
        s0 = fmaf(a1.w, a1.w, s0);   s1 = fmaf(a1.w, b1.w, s1);

        #pragma unroll
        for (int o = 16; o > 0; o >>= 1) {
            s0 += __shfl_xor_sync(0xFFFFFFFFu, s0, o);
            s1 += __shfl_xor_sync(0xFFFFFFFFu, s1, o);
        }

        const int buf = (iter & 1) << 3;    // 0 or 8
        if (lane == 0) { sh0[buf + w] = s0; sh1[buf + w] = s1; }
        __syncthreads();                     // single sync per row

        if (tid == 0) {
            float r0 = sh0[buf], r1 = sh1[buf];
            #pragma unroll
            for (int k = 1; k < 8; k++) { r0 += sh0[buf + k]; r1 += sh1[buf + k]; }

            const float diff = (r0 - r1) * TEMP_INV;
            const float p = 1.0f / (1.0f + expf(-diff));
            const float label = (y[i] != y[j]) ? 1.0f : 0.0f;
            blockLoss += -logf(p + EPS) * label
                         - logf(1.0f - p + EPS) * (1.0f - label);
        }
    }

    if (tid == 0 && blockLoss != 0.0f)
        atomicAdd(&g_accum, blockLoss);
    else if (tid == 0)
        atomicAdd(&g_accum, blockLoss);   // keep deterministic add count
}

__global__ void finalize_kernel(float* __restrict__ out, float invB) {
    if (threadIdx.x == 0) {
        out[0] = g_accum * invB;
        g_accum = 0.0f;                   // reset for next graph replay
    }
}

extern "C" void kernel_launch(void* const* d_in, const int* in_sizes, int n_in,
                              void* d_out, int out_size)
{
    const float* x       = (const float*)d_in[0];
    const int*   y       = (const int*)d_in[1];
    const int*   samples = (const int*)d_in[2];
    float* out = (float*)d_out;

    const int B = in_sizes[1];                 // 16384
    const int D = in_sizes[0] / in_sizes[1];   // 2048

    int blocks = 148 * 8;                      // persistent: fills every SM
    if (blocks > B) blocks = B;

    loss_kernel<<<blocks, 256>>>(x, y, samples, B, D);
    finalize_kernel<<<1, 32>>>(out, 1.0f / (float)B);
}